// round 7
// baseline (speedup 1.0000x reference)
#include <cuda_runtime.h>
#include <cuda_fp16.h>
#include <cstdint>

// ============================================================================
// Problem constants
// ============================================================================
#define OUTF 4096   // out_features (M)
#define INF  4096   // in_features  (K)
#define NCOLS 8192  // N

// Dense scratch (allocation-free: __device__ globals). 192 MB total.
__device__ float  g_W  [(size_t)OUTF * INF];   // 64 MB dense fp32 weight
__device__ __half g_Whi[(size_t)OUTF * INF];   // 32 MB hi fp16 plane
__device__ __half g_Wlo[(size_t)OUTF * INF];   // 32 MB lo (residual) fp16 plane
__device__ __half g_xh [(size_t)INF * NCOLS];  // 64 MB x in fp16, same [K, N] layout

// ============================================================================
// Generic (non-arch-specific) PTX helpers — safe for .target sm_103
// ============================================================================
__device__ __forceinline__ uint32_t smem_u32(const void* p) {
    uint32_t a;
    asm("{ .reg .u64 t; cvta.to.shared.u64 t, %1; cvt.u32.u64 %0, t; }" : "=r"(a) : "l"(p));
    return a;
}

__device__ __forceinline__ void cp_async16(uint32_t dst, const void* src) {
    asm volatile("cp.async.cg.shared.global [%0], [%1], 16;\n" :: "r"(dst), "l"(src) : "memory");
}

__device__ __forceinline__ void cp_commit() {
    asm volatile("cp.async.commit_group;\n" ::: "memory");
}

template <int N>
__device__ __forceinline__ void cp_wait_group() {
    asm volatile("cp.async.wait_group %0;\n" :: "n"(N) : "memory");
}

__device__ __forceinline__ void ldmatrix_x4(uint32_t* r, uint32_t addr) {
    asm volatile("ldmatrix.sync.aligned.m8n8.x4.shared.b16 {%0,%1,%2,%3}, [%4];\n"
                 : "=r"(r[0]), "=r"(r[1]), "=r"(r[2]), "=r"(r[3]) : "r"(addr));
}

__device__ __forceinline__ void ldmatrix_x4_t(uint32_t* r, uint32_t addr) {
    asm volatile("ldmatrix.sync.aligned.m8n8.x4.trans.shared.b16 {%0,%1,%2,%3}, [%4];\n"
                 : "=r"(r[0]), "=r"(r[1]), "=r"(r[2]), "=r"(r[3]) : "r"(addr));
}

__device__ __forceinline__ void mma16816(float* d, const uint32_t* a, const uint32_t* b) {
    asm volatile(
        "mma.sync.aligned.m16n8k16.row.col.f32.f16.f16.f32 "
        "{%0,%1,%2,%3}, {%4,%5,%6,%7}, {%8,%9}, {%0,%1,%2,%3};\n"
        : "+f"(d[0]), "+f"(d[1]), "+f"(d[2]), "+f"(d[3])
        : "r"(a[0]), "r"(a[1]), "r"(a[2]), "r"(a[3]), "r"(b[0]), "r"(b[1]));
}

// ============================================================================
// Phase 1: zero dense W
// ============================================================================
__global__ void zero_w_kernel() {
    size_t n4 = (size_t)OUTF * INF / 4;
    float4 z = make_float4(0.f, 0.f, 0.f, 0.f);
    for (size_t i = (size_t)blockIdx.x * blockDim.x + threadIdx.x; i < n4;
         i += (size_t)gridDim.x * blockDim.x)
        reinterpret_cast<float4*>(g_W)[i] = z;
}

// ============================================================================
// Phase 2: scatter COO (duplicates sum via atomicAdd, matching reference)
// ============================================================================
__global__ void scatter_kernel(const int* __restrict__ rows, const int* __restrict__ cols,
                               const float* __restrict__ vals, int nnz) {
    int i = blockIdx.x * blockDim.x + threadIdx.x;
    if (i < nnz)
        atomicAdd(&g_W[(size_t)rows[i] * INF + cols[i]], vals[i]);
}

// ============================================================================
// Phase 3a: split W fp32 -> hi/lo fp16 planes (exact-to-fp16-pair precision)
// ============================================================================
__global__ void split_w_kernel() {
    size_t n4 = (size_t)OUTF * INF / 4;
    for (size_t i = (size_t)blockIdx.x * blockDim.x + threadIdx.x; i < n4;
         i += (size_t)gridDim.x * blockDim.x) {
        float4 v = reinterpret_cast<const float4*>(g_W)[i];
        __half h0 = __float2half_rn(v.x), h1 = __float2half_rn(v.y);
        __half h2 = __float2half_rn(v.z), h3 = __float2half_rn(v.w);
        __half l0 = __float2half_rn(v.x - __half2float(h0));
        __half l1 = __float2half_rn(v.y - __half2float(h1));
        __half l2 = __float2half_rn(v.z - __half2float(h2));
        __half l3 = __float2half_rn(v.w - __half2float(h3));
        __half2 hA = __halves2half2(h0, h1), hB = __halves2half2(h2, h3);
        __half2 lA = __halves2half2(l0, l1), lB = __halves2half2(l2, l3);
        uint2 hw, lw;
        hw.x = *reinterpret_cast<uint32_t*>(&hA);
        hw.y = *reinterpret_cast<uint32_t*>(&hB);
        lw.x = *reinterpret_cast<uint32_t*>(&lA);
        lw.y = *reinterpret_cast<uint32_t*>(&lB);
        reinterpret_cast<uint2*>(g_Whi)[i] = hw;
        reinterpret_cast<uint2*>(g_Wlo)[i] = lw;
    }
}

// ============================================================================
// Phase 3b: elementwise fp16 convert of x (layout preserved: [K, N], N-contig)
// ============================================================================
__global__ void convert_x_kernel(const float* __restrict__ x) {
    size_t n4 = (size_t)INF * NCOLS / 4;
    for (size_t i = (size_t)blockIdx.x * blockDim.x + threadIdx.x; i < n4;
         i += (size_t)gridDim.x * blockDim.x) {
        float4 v = reinterpret_cast<const float4*>(x)[i];
        __half2 a = __halves2half2(__float2half_rn(v.x), __float2half_rn(v.y));
        __half2 b = __halves2half2(__float2half_rn(v.z), __float2half_rn(v.w));
        uint2 w;
        w.x = *reinterpret_cast<uint32_t*>(&a);
        w.y = *reinterpret_cast<uint32_t*>(&b);
        reinterpret_cast<uint2*>(g_xh)[i] = w;
    }
}

// ============================================================================
// Phase 4: mma.sync fp16 GEMM, BM=128 BN=128 BK=32, 4-stage cp.async pipeline.
// out[m, n] = sum_k (Whi[m,k] + Wlo[m,k]) * fp16(x[k, n]),  fp32 accumulate.
// ============================================================================
static constexpr int BM = 128, BN = 128, BK = 32, STAGES = 4;
static constexpr int SA = BM * BK * 2;            // 8192 B per A plane
static constexpr int SB = BK * BN * 2;            // 8192 B
static constexpr int STAGE_BYTES = 2 * SA + SB;   // 24576 B
static constexpr int SMEM_BYTES = STAGE_BYTES * STAGES;  // 98304 B
static constexpr int NK = INF / BK;               // 128

__global__ void __launch_bounds__(256, 1)
gemm_kernel(float* __restrict__ out) {
    extern __shared__ __align__(128) char smem[];
    const uint32_t sbase = smem_u32(smem);
    const int tid = threadIdx.x;
    const int lane = tid & 31;
    const int wid = tid >> 5;
    const int wm = wid & 1;    // 2 warps along M
    const int wn = wid >> 1;   // 4 warps along N
    const int m0 = blockIdx.y * BM;
    const int n0 = blockIdx.x * BN;

    const __half* Ahi = g_Whi + (size_t)m0 * INF;
    const __half* Alo = g_Wlo + (size_t)m0 * INF;
    const __half* Bx  = g_xh + n0;

    float acc[4][4][4];
    #pragma unroll
    for (int i = 0; i < 4; ++i)
        #pragma unroll
        for (int j = 0; j < 4; ++j)
            #pragma unroll
            for (int r = 0; r < 4; ++r) acc[i][j][r] = 0.f;

    // ---- stage loader: A (hi+lo) K-major 64B rows; B N-contig 256B rows.
    auto load_stage = [&](int slot, int kt) {
        const uint32_t s = sbase + slot * STAGE_BYTES;
        const int k0 = kt * BK;
        #pragma unroll
        for (int it = 0; it < 2; ++it) {
            int idx = it * 256 + tid;
            int row = idx >> 2, c = idx & 3;                         // 4 x 16B chunks / row
            uint32_t dst = s + row * 64 + ((c ^ ((row >> 1) & 3)) << 4);
            cp_async16(dst,      Ahi + (size_t)row * INF + k0 + c * 8);
            cp_async16(dst + SA, Alo + (size_t)row * INF + k0 + c * 8);
        }
        #pragma unroll
        for (int it = 0; it < 2; ++it) {
            int idx = it * 256 + tid;
            int k = idx >> 4, c = idx & 15;                          // 16 x 16B chunks / row
            uint32_t dst = s + 2 * SA + k * 256 + ((c ^ (k & 7)) << 4);
            cp_async16(dst, Bx + (size_t)(k0 + k) * NCOLS + c * 8);
        }
        cp_commit();
    };

    // ---- prologue
    #pragma unroll
    for (int st = 0; st < STAGES - 1; ++st) load_stage(st, st);

    const int r16 = lane & 15;
    const int hi16 = lane >> 4;

    for (int kt = 0; kt < NK; ++kt) {
        cp_wait_group<STAGES - 2>();
        __syncthreads();

        const uint32_t s = sbase + (kt & (STAGES - 1)) * STAGE_BYTES;
        const uint32_t sAhi = s, sAlo = s + SA, sBm = s + 2 * SA;

        #pragma unroll
        for (int ks = 0; ks < 2; ++ks) {
            const int kk = ks * 16;
            uint32_t ah[4][4], al[4][4], bb[4][2];
            // A fragments (row-major, non-trans ldmatrix)
            #pragma unroll
            for (int mt = 0; mt < 4; ++mt) {
                int row = wm * 64 + mt * 16 + r16;
                int c = (kk >> 3) + hi16;
                uint32_t off = row * 64 + ((c ^ ((row >> 1) & 3)) << 4);
                ldmatrix_x4(ah[mt], sAhi + off);
                ldmatrix_x4(al[mt], sAlo + off);
            }
            // B fragments (N-contig rows, trans ldmatrix)
            #pragma unroll
            for (int nb = 0; nb < 2; ++nb) {
                int k = kk + r16;
                int c = ((wn * 32 + nb * 16) >> 3) + hi16;
                uint32_t t[4];
                ldmatrix_x4_t(t, sBm + k * 256 + ((c ^ (k & 7)) << 4));
                bb[nb * 2][0] = t[0]; bb[nb * 2][1] = t[1];
                bb[nb * 2 + 1][0] = t[2]; bb[nb * 2 + 1][1] = t[3];
            }
            // MMAs: both planes share B fragments
            #pragma unroll
            for (int mt = 0; mt < 4; ++mt)
                #pragma unroll
                for (int nt = 0; nt < 4; ++nt) {
                    mma16816(acc[mt][nt], ah[mt], bb[nt]);
                    mma16816(acc[mt][nt], al[mt], bb[nt]);
                }
        }

        const int nx = kt + STAGES - 1;
        if (nx < NK) load_stage(nx & (STAGES - 1), nx);
        else cp_commit();  // keep group count consistent
    }

    // ---- epilogue: mma accum layout -> float2 stores
    const int r4 = lane >> 2, c2 = lane & 3;
    #pragma unroll
    for (int mt = 0; mt < 4; ++mt) {
        int gm = m0 + wm * 64 + mt * 16 + r4;
        #pragma unroll
        for (int nt = 0; nt < 4; ++nt) {
            int gn = n0 + wn * 32 + nt * 8 + c2 * 2;
            float2 v0 = make_float2(acc[mt][nt][0], acc[mt][nt][1]);
            float2 v1 = make_float2(acc[mt][nt][2], acc[mt][nt][3]);
            *reinterpret_cast<float2*>(&out[(size_t)gm * NCOLS + gn]) = v0;
            *reinterpret_cast<float2*>(&out[(size_t)(gm + 8) * NCOLS + gn]) = v1;
        }
    }
}

// ============================================================================
// Launch
// ============================================================================
extern "C" void kernel_launch(void* const* d_in, const int* in_sizes, int n_in,
                              void* d_out, int out_size) {
    const int*   rows = (const int*)d_in[0];
    const int*   cols = (const int*)d_in[1];
    const float* vals = (const float*)d_in[2];
    const float* x    = (const float*)d_in[3];
    const int nnz = in_sizes[0];

    // Unconditional (no static guards — harness contract). Idempotent and
    // graph-capture-safe: not a stream operation.
    cudaFuncSetAttribute(gemm_kernel, cudaFuncAttributeMaxDynamicSharedMemorySize,
                         SMEM_BYTES);

    zero_w_kernel<<<2048, 256>>>();
    scatter_kernel<<<(nnz + 255) / 256, 256>>>(rows, cols, vals, nnz);
    split_w_kernel<<<2048, 256>>>();
    convert_x_kernel<<<2048, 256>>>(x);
    gemm_kernel<<<dim3(NCOLS / BN, OUTF / BM), 256, SMEM_BYTES>>>((float*)d_out);
}

// round 9
// speedup vs baseline: 1.8294x; 1.8294x over previous
#include <cuda_runtime.h>
#include <cuda_fp16.h>
#include <cstdint>

// ============================================================================
// Problem constants
// ============================================================================
#define OUTF 4096   // out_features (M)
#define INF  4096   // in_features  (K)
#define NCOLS 8192  // N

// Dense scratch (allocation-free: __device__ globals). 160 MB total.
__device__ float  g_W [(size_t)OUTF * INF];    // 64 MB dense fp32 weight
__device__ __half g_Wh[(size_t)OUTF * INF];    // 32 MB fp16 weight
__device__ __half g_xh[(size_t)INF * NCOLS];   // 64 MB x in fp16, [K, N] layout

// ============================================================================
// Generic (non-arch-specific) PTX helpers — safe for .target sm_103
// ============================================================================
__device__ __forceinline__ uint32_t smem_u32(const void* p) {
    uint32_t a;
    asm("{ .reg .u64 t; cvta.to.shared.u64 t, %1; cvt.u32.u64 %0, t; }" : "=r"(a) : "l"(p));
    return a;
}

__device__ __forceinline__ void cp_async16(uint32_t dst, const void* src) {
    asm volatile("cp.async.cg.shared.global [%0], [%1], 16;\n" :: "r"(dst), "l"(src) : "memory");
}

__device__ __forceinline__ void cp_commit() {
    asm volatile("cp.async.commit_group;\n" ::: "memory");
}

template <int N>
__device__ __forceinline__ void cp_wait_group() {
    asm volatile("cp.async.wait_group %0;\n" :: "n"(N) : "memory");
}

__device__ __forceinline__ void ldmatrix_x4(uint32_t* r, uint32_t addr) {
    asm volatile("ldmatrix.sync.aligned.m8n8.x4.shared.b16 {%0,%1,%2,%3}, [%4];\n"
                 : "=r"(r[0]), "=r"(r[1]), "=r"(r[2]), "=r"(r[3]) : "r"(addr));
}

__device__ __forceinline__ void ldmatrix_x4_t(uint32_t* r, uint32_t addr) {
    asm volatile("ldmatrix.sync.aligned.m8n8.x4.trans.shared.b16 {%0,%1,%2,%3}, [%4];\n"
                 : "=r"(r[0]), "=r"(r[1]), "=r"(r[2]), "=r"(r[3]) : "r"(addr));
}

__device__ __forceinline__ void mma16816(float* d, const uint32_t* a, const uint32_t* b) {
    asm volatile(
        "mma.sync.aligned.m16n8k16.row.col.f32.f16.f16.f32 "
        "{%0,%1,%2,%3}, {%4,%5,%6,%7}, {%8,%9}, {%0,%1,%2,%3};\n"
        : "+f"(d[0]), "+f"(d[1]), "+f"(d[2]), "+f"(d[3])
        : "r"(a[0]), "r"(a[1]), "r"(a[2]), "r"(a[3]), "r"(b[0]), "r"(b[1]));
}

// ============================================================================
// Phase 1: zero dense W
// ============================================================================
__global__ void zero_w_kernel() {
    size_t n4 = (size_t)OUTF * INF / 4;
    float4 z = make_float4(0.f, 0.f, 0.f, 0.f);
    for (size_t i = (size_t)blockIdx.x * blockDim.x + threadIdx.x; i < n4;
         i += (size_t)gridDim.x * blockDim.x)
        reinterpret_cast<float4*>(g_W)[i] = z;
}

// ============================================================================
// Phase 2: scatter COO (duplicates sum via atomicAdd, matching reference)
// ============================================================================
__global__ void scatter_kernel(const int* __restrict__ rows, const int* __restrict__ cols,
                               const float* __restrict__ vals, int nnz) {
    int i = blockIdx.x * blockDim.x + threadIdx.x;
    if (i < nnz)
        atomicAdd(&g_W[(size_t)rows[i] * INF + cols[i]], vals[i]);
}

// ============================================================================
// Phase 3a: convert W fp32 -> fp16 (single plane)
// ============================================================================
__global__ void convert_w_kernel() {
    size_t n4 = (size_t)OUTF * INF / 4;
    for (size_t i = (size_t)blockIdx.x * blockDim.x + threadIdx.x; i < n4;
         i += (size_t)gridDim.x * blockDim.x) {
        float4 v = reinterpret_cast<const float4*>(g_W)[i];
        __half2 a = __halves2half2(__float2half_rn(v.x), __float2half_rn(v.y));
        __half2 b = __halves2half2(__float2half_rn(v.z), __float2half_rn(v.w));
        uint2 w;
        w.x = *reinterpret_cast<uint32_t*>(&a);
        w.y = *reinterpret_cast<uint32_t*>(&b);
        reinterpret_cast<uint2*>(g_Wh)[i] = w;
    }
}

// ============================================================================
// Phase 3b: elementwise fp16 convert of x (layout preserved: [K, N], N-contig)
// ============================================================================
__global__ void convert_x_kernel(const float* __restrict__ x) {
    size_t n4 = (size_t)INF * NCOLS / 4;
    for (size_t i = (size_t)blockIdx.x * blockDim.x + threadIdx.x; i < n4;
         i += (size_t)gridDim.x * blockDim.x) {
        float4 v = reinterpret_cast<const float4*>(x)[i];
        __half2 a = __halves2half2(__float2half_rn(v.x), __float2half_rn(v.y));
        __half2 b = __halves2half2(__float2half_rn(v.z), __float2half_rn(v.w));
        uint2 w;
        w.x = *reinterpret_cast<uint32_t*>(&a);
        w.y = *reinterpret_cast<uint32_t*>(&b);
        reinterpret_cast<uint2*>(g_xh)[i] = w;
    }
}

// ============================================================================
// Phase 4: mma.sync fp16 GEMM, BM=256 BN=128 BK=32, 512 thr, 4-stage cp.async.
// out[m, n] = sum_k Wh[m,k] * xh[k, n],  fp32 accumulate.
// 16 warps in a 4(M) x 4(N) grid, 64x32 warp tiles.
// ============================================================================
static constexpr int BM = 256, BN = 128, BK = 32, STAGES = 4;
static constexpr int SA = BM * BK * 2;            // 16384 B
static constexpr int SB = BK * BN * 2;            // 8192 B
static constexpr int STAGE_BYTES = SA + SB;       // 24576 B
static constexpr int SMEM_BYTES = STAGE_BYTES * STAGES;  // 98304 B
static constexpr int NK = INF / BK;               // 128

__global__ void __launch_bounds__(512, 1)
gemm_kernel(float* __restrict__ out) {
    extern __shared__ __align__(128) char smem[];
    const uint32_t sbase = smem_u32(smem);
    const int tid = threadIdx.x;
    const int lane = tid & 31;
    const int wid = tid >> 5;
    const int wm = wid & 3;    // 4 warps along M (4 x 64 = 256)
    const int wn = wid >> 2;   // 4 warps along N (4 x 32 = 128)
    const int m0 = blockIdx.y * BM;
    const int n0 = blockIdx.x * BN;

    const __half* Aw = g_Wh + (size_t)m0 * INF;
    const __half* Bx = g_xh + n0;

    float acc[4][4][4];
    #pragma unroll
    for (int i = 0; i < 4; ++i)
        #pragma unroll
        for (int j = 0; j < 4; ++j)
            #pragma unroll
            for (int r = 0; r < 4; ++r) acc[i][j][r] = 0.f;

    // ---- stage loader: A K-major 64B rows; B N-contig 256B rows.
    auto load_stage = [&](int slot, int kt) {
        const uint32_t s = sbase + slot * STAGE_BYTES;
        const int k0 = kt * BK;
        // A: 256 rows x 4 chunks of 16B = 1024 chunks -> 2 per thread
        #pragma unroll
        for (int it = 0; it < 2; ++it) {
            int idx = it * 512 + tid;
            int row = idx >> 2, c = idx & 3;
            uint32_t dst = s + row * 64 + ((c ^ ((row >> 1) & 3)) << 4);
            cp_async16(dst, Aw + (size_t)row * INF + k0 + c * 8);
        }
        // B: 32 k-rows x 16 chunks of 16B = 512 chunks -> 1 per thread
        {
            int k = tid >> 4, c = tid & 15;
            uint32_t dst = s + SA + k * 256 + ((c ^ (k & 7)) << 4);
            cp_async16(dst, Bx + (size_t)(k0 + k) * NCOLS + c * 8);
        }
        cp_commit();
    };

    // ---- prologue
    #pragma unroll
    for (int st = 0; st < STAGES - 1; ++st) load_stage(st, st);

    const int r16 = lane & 15;
    const int hi16 = lane >> 4;

    for (int kt = 0; kt < NK; ++kt) {
        cp_wait_group<STAGES - 2>();
        __syncthreads();

        const uint32_t s = sbase + (kt & (STAGES - 1)) * STAGE_BYTES;
        const uint32_t sA = s, sBm = s + SA;

        #pragma unroll
        for (int ks = 0; ks < 2; ++ks) {
            const int kk = ks * 16;
            uint32_t ah[4][4], bb[4][2];
            // A fragments (row-major, non-trans ldmatrix): 16x16 each
            #pragma unroll
            for (int mt = 0; mt < 4; ++mt) {
                int row = wm * 64 + mt * 16 + r16;
                int c = (kk >> 3) + hi16;
                uint32_t off = row * 64 + ((c ^ ((row >> 1) & 3)) << 4);
                ldmatrix_x4(ah[mt], sA + off);
            }
            // B fragments (N-contig rows, trans ldmatrix): 16k x 16n each
            #pragma unroll
            for (int nb = 0; nb < 2; ++nb) {
                int k = kk + r16;
                int c = ((wn * 32 + nb * 16) >> 3) + hi16;
                uint32_t t[4];
                ldmatrix_x4_t(t, sBm + k * 256 + ((c ^ (k & 7)) << 4));
                bb[nb * 2][0] = t[0]; bb[nb * 2][1] = t[1];
                bb[nb * 2 + 1][0] = t[2]; bb[nb * 2 + 1][1] = t[3];
            }
            #pragma unroll
            for (int mt = 0; mt < 4; ++mt)
                #pragma unroll
                for (int nt = 0; nt < 4; ++nt)
                    mma16816(acc[mt][nt], ah[mt], bb[nt]);
        }

        const int nx = kt + STAGES - 1;
        if (nx < NK) load_stage(nx & (STAGES - 1), nx);
        else cp_commit();  // keep group count consistent
    }

    // ---- epilogue: mma accum layout -> float2 stores
    const int r4 = lane >> 2, c2 = lane & 3;
    #pragma unroll
    for (int mt = 0; mt < 4; ++mt) {
        int gm = m0 + wm * 64 + mt * 16 + r4;
        #pragma unroll
        for (int nt = 0; nt < 4; ++nt) {
            int gn = n0 + wn * 32 + nt * 8 + c2 * 2;
            float2 v0 = make_float2(acc[mt][nt][0], acc[mt][nt][1]);
            float2 v1 = make_float2(acc[mt][nt][2], acc[mt][nt][3]);
            *reinterpret_cast<float2*>(&out[(size_t)gm * NCOLS + gn]) = v0;
            *reinterpret_cast<float2*>(&out[(size_t)(gm + 8) * NCOLS + gn]) = v1;
        }
    }
}

// ============================================================================
// Launch
// ============================================================================
extern "C" void kernel_launch(void* const* d_in, const int* in_sizes, int n_in,
                              void* d_out, int out_size) {
    const int*   rows = (const int*)d_in[0];
    const int*   cols = (const int*)d_in[1];
    const float* vals = (const float*)d_in[2];
    const float* x    = (const float*)d_in[3];
    const int nnz = in_sizes[0];

    // Unconditional (no static guards — harness contract). Idempotent and
    // graph-capture-safe: not a stream operation.
    cudaFuncSetAttribute(gemm_kernel, cudaFuncAttributeMaxDynamicSharedMemorySize,
                         SMEM_BYTES);

    zero_w_kernel<<<2048, 256>>>();
    scatter_kernel<<<(nnz + 255) / 256, 256>>>(rows, cols, vals, nnz);
    convert_w_kernel<<<2048, 256>>>();
    convert_x_kernel<<<2048, 256>>>(x);
    gemm_kernel<<<dim3(NCOLS / BN, OUTF / BM), 512, SMEM_BYTES>>>((float*)d_out);
}

// round 10
// speedup vs baseline: 1.8417x; 1.0067x over previous
#include <cuda_runtime.h>
#include <cuda_fp16.h>
#include <cstdint>

// ============================================================================
// Problem constants
// ============================================================================
#define OUTF 4096   // out_features (M)
#define INF  4096   // in_features  (K)
#define NCOLS 8192  // N

// Dense scratch (allocation-free: __device__ globals). 96 MB total.
__device__ __half g_Wh[(size_t)OUTF * INF];    // 32 MB fp16 weight (scatter target)
__device__ __half g_xh[(size_t)INF * NCOLS];   // 64 MB x in fp16, [K, N] layout

// ============================================================================
// Generic (non-arch-specific) PTX helpers — safe for .target sm_103
// ============================================================================
__device__ __forceinline__ uint32_t smem_u32(const void* p) {
    uint32_t a;
    asm("{ .reg .u64 t; cvta.to.shared.u64 t, %1; cvt.u32.u64 %0, t; }" : "=r"(a) : "l"(p));
    return a;
}

__device__ __forceinline__ void cp_async16(uint32_t dst, const void* src) {
    asm volatile("cp.async.cg.shared.global [%0], [%1], 16;\n" :: "r"(dst), "l"(src) : "memory");
}

__device__ __forceinline__ void cp_commit() {
    asm volatile("cp.async.commit_group;\n" ::: "memory");
}

template <int N>
__device__ __forceinline__ void cp_wait_group() {
    asm volatile("cp.async.wait_group %0;\n" :: "n"(N) : "memory");
}

__device__ __forceinline__ void ldmatrix_x4(uint32_t* r, uint32_t addr) {
    asm volatile("ldmatrix.sync.aligned.m8n8.x4.shared.b16 {%0,%1,%2,%3}, [%4];\n"
                 : "=r"(r[0]), "=r"(r[1]), "=r"(r[2]), "=r"(r[3]) : "r"(addr));
}

__device__ __forceinline__ void ldmatrix_x4_t(uint32_t* r, uint32_t addr) {
    asm volatile("ldmatrix.sync.aligned.m8n8.x4.trans.shared.b16 {%0,%1,%2,%3}, [%4];\n"
                 : "=r"(r[0]), "=r"(r[1]), "=r"(r[2]), "=r"(r[3]) : "r"(addr));
}

__device__ __forceinline__ void mma16816(float* d, const uint32_t* a, const uint32_t* b) {
    asm volatile(
        "mma.sync.aligned.m16n8k16.row.col.f32.f16.f16.f32 "
        "{%0,%1,%2,%3}, {%4,%5,%6,%7}, {%8,%9}, {%0,%1,%2,%3};\n"
        : "+f"(d[0]), "+f"(d[1]), "+f"(d[2]), "+f"(d[3])
        : "r"(a[0]), "r"(a[1]), "r"(a[2]), "r"(a[3]), "r"(b[0]), "r"(b[1]));
}

// ============================================================================
// Phase 1: zero fp16 W
// ============================================================================
__global__ void zero_wh_kernel() {
    size_t n8 = (size_t)OUTF * INF / 8;   // uint4 = 8 halves
    uint4 z = make_uint4(0u, 0u, 0u, 0u);
    for (size_t i = (size_t)blockIdx.x * blockDim.x + threadIdx.x; i < n8;
         i += (size_t)gridDim.x * blockDim.x)
        reinterpret_cast<uint4*>(g_Wh)[i] = z;
}

// ============================================================================
// Phase 2: scatter COO directly into fp16 (duplicates sum via f16 atomicAdd;
// non-duplicates get identical rounding to fp32-scatter-then-convert)
// ============================================================================
__global__ void scatter_kernel(const int* __restrict__ rows, const int* __restrict__ cols,
                               const float* __restrict__ vals, int nnz) {
    int i = blockIdx.x * blockDim.x + threadIdx.x;
    if (i < nnz)
        atomicAdd(&g_Wh[(size_t)rows[i] * INF + cols[i]], __float2half_rn(vals[i]));
}

// ============================================================================
// Phase 3: elementwise fp16 convert of x (layout preserved: [K, N], N-contig)
// ============================================================================
__global__ void convert_x_kernel(const float* __restrict__ x) {
    size_t n4 = (size_t)INF * NCOLS / 4;
    for (size_t i = (size_t)blockIdx.x * blockDim.x + threadIdx.x; i < n4;
         i += (size_t)gridDim.x * blockDim.x) {
        float4 v = reinterpret_cast<const float4*>(x)[i];
        __half2 a = __halves2half2(__float2half_rn(v.x), __float2half_rn(v.y));
        __half2 b = __halves2half2(__float2half_rn(v.z), __float2half_rn(v.w));
        uint2 w;
        w.x = *reinterpret_cast<uint32_t*>(&a);
        w.y = *reinterpret_cast<uint32_t*>(&b);
        reinterpret_cast<uint2*>(g_xh)[i] = w;
    }
}

// ============================================================================
// Phase 4: mma.sync fp16 GEMM, BM=256 BN=128 BK=32, 256 thr, 4-stage cp.async.
// 8 warps in a 4(M) x 2(N) grid, 64x64 warp tiles (halves LDSM redundancy).
// out[m, n] = sum_k Wh[m,k] * xh[k, n],  fp32 accumulate.
// ============================================================================
static constexpr int BM = 256, BN = 128, BK = 32, STAGES = 4;
static constexpr int SA = BM * BK * 2;            // 16384 B
static constexpr int SB = BK * BN * 2;            // 8192 B
static constexpr int STAGE_BYTES = SA + SB;       // 24576 B
static constexpr int SMEM_BYTES = STAGE_BYTES * STAGES;  // 98304 B
static constexpr int NK = INF / BK;               // 128

__global__ void __launch_bounds__(256, 1)
gemm_kernel(float* __restrict__ out) {
    extern __shared__ __align__(128) char smem[];
    const uint32_t sbase = smem_u32(smem);
    const int tid = threadIdx.x;
    const int lane = tid & 31;
    const int wid = tid >> 5;
    const int wm = wid & 3;    // 4 warps along M (4 x 64 = 256)
    const int wn = wid >> 2;   // 2 warps along N (2 x 64 = 128)
    const int m0 = blockIdx.y * BM;
    const int n0 = blockIdx.x * BN;

    const __half* Aw = g_Wh + (size_t)m0 * INF;
    const __half* Bx = g_xh + n0;

    float acc[4][8][4];
    #pragma unroll
    for (int i = 0; i < 4; ++i)
        #pragma unroll
        for (int j = 0; j < 8; ++j)
            #pragma unroll
            for (int r = 0; r < 4; ++r) acc[i][j][r] = 0.f;

    // ---- stage loader: A K-major 64B rows; B N-contig 256B rows.
    auto load_stage = [&](int slot, int kt) {
        const uint32_t s = sbase + slot * STAGE_BYTES;
        const int k0 = kt * BK;
        // A: 256 rows x 4 chunks of 16B = 1024 chunks -> 4 per thread
        #pragma unroll
        for (int it = 0; it < 4; ++it) {
            int idx = it * 256 + tid;
            int row = idx >> 2, c = idx & 3;
            uint32_t dst = s + row * 64 + ((c ^ ((row >> 1) & 3)) << 4);
            cp_async16(dst, Aw + (size_t)row * INF + k0 + c * 8);
        }
        // B: 32 k-rows x 16 chunks of 16B = 512 chunks -> 2 per thread
        #pragma unroll
        for (int it = 0; it < 2; ++it) {
            int idx = it * 256 + tid;
            int k = idx >> 4, c = idx & 15;
            uint32_t dst = s + SA + k * 256 + ((c ^ (k & 7)) << 4);
            cp_async16(dst, Bx + (size_t)(k0 + k) * NCOLS + c * 8);
        }
        cp_commit();
    };

    // ---- prologue
    #pragma unroll
    for (int st = 0; st < STAGES - 1; ++st) load_stage(st, st);

    const int r16 = lane & 15;
    const int hi16 = lane >> 4;

    for (int kt = 0; kt < NK; ++kt) {
        cp_wait_group<STAGES - 2>();
        __syncthreads();

        const uint32_t s = sbase + (kt & (STAGES - 1)) * STAGE_BYTES;
        const uint32_t sA = s, sBm = s + SA;

        #pragma unroll
        for (int ks = 0; ks < 2; ++ks) {
            const int kk = ks * 16;
            uint32_t ah[4][4], bb[8][2];
            // A fragments (row-major, non-trans ldmatrix): 16x16 each
            #pragma unroll
            for (int mt = 0; mt < 4; ++mt) {
                int row = wm * 64 + mt * 16 + r16;
                int c = (kk >> 3) + hi16;
                uint32_t off = row * 64 + ((c ^ ((row >> 1) & 3)) << 4);
                ldmatrix_x4(ah[mt], sA + off);
            }
            // B fragments (N-contig rows, trans ldmatrix): 16k x 16n each
            #pragma unroll
            for (int nb = 0; nb < 4; ++nb) {
                int k = kk + r16;
                int c = ((wn * 64 + nb * 16) >> 3) + hi16;
                uint32_t t[4];
                ldmatrix_x4_t(t, sBm + k * 256 + ((c ^ (k & 7)) << 4));
                bb[nb * 2][0] = t[0]; bb[nb * 2][1] = t[1];
                bb[nb * 2 + 1][0] = t[2]; bb[nb * 2 + 1][1] = t[3];
            }
            #pragma unroll
            for (int mt = 0; mt < 4; ++mt)
                #pragma unroll
                for (int nt = 0; nt < 8; ++nt)
                    mma16816(acc[mt][nt], ah[mt], bb[nt]);
        }

        const int nx = kt + STAGES - 1;
        if (nx < NK) load_stage(nx & (STAGES - 1), nx);
        else cp_commit();  // keep group count consistent
    }

    // ---- epilogue: mma accum layout -> float2 stores
    const int r4 = lane >> 2, c2 = lane & 3;
    #pragma unroll
    for (int mt = 0; mt < 4; ++mt) {
        int gm = m0 + wm * 64 + mt * 16 + r4;
        #pragma unroll
        for (int nt = 0; nt < 8; ++nt) {
            int gn = n0 + wn * 64 + nt * 8 + c2 * 2;
            float2 v0 = make_float2(acc[mt][nt][0], acc[mt][nt][1]);
            float2 v1 = make_float2(acc[mt][nt][2], acc[mt][nt][3]);
            *reinterpret_cast<float2*>(&out[(size_t)gm * NCOLS + gn]) = v0;
            *reinterpret_cast<float2*>(&out[(size_t)(gm + 8) * NCOLS + gn]) = v1;
        }
    }
}

// ============================================================================
// Launch
// ============================================================================
extern "C" void kernel_launch(void* const* d_in, const int* in_sizes, int n_in,
                              void* d_out, int out_size) {
    const int*   rows = (const int*)d_in[0];
    const int*   cols = (const int*)d_in[1];
    const float* vals = (const float*)d_in[2];
    const float* x    = (const float*)d_in[3];
    const int nnz = in_sizes[0];

    // Unconditional (no static guards — harness contract). Idempotent and
    // graph-capture-safe: not a stream operation.
    cudaFuncSetAttribute(gemm_kernel, cudaFuncAttributeMaxDynamicSharedMemorySize,
                         SMEM_BYTES);

    zero_wh_kernel<<<2048, 256>>>();
    scatter_kernel<<<(nnz + 255) / 256, 256>>>(rows, cols, vals, nnz);
    convert_x_kernel<<<2048, 256>>>(x);
    gemm_kernel<<<dim3(NCOLS / BN, OUTF / BM), 256, SMEM_BYTES>>>((float*)d_out);
}